// round 1
// baseline (speedup 1.0000x reference)
#include <cuda_runtime.h>
#include <cstdint>
#include <cstddef>

#define NN 3072
#define FIN 512
#define FOUT 256

// ---------------- scratch (device globals: no allocation allowed) -------------
__device__ __align__(128) float g_XR[NN * NN];
__device__ __align__(128) float g_XI[NN * NN];
__device__ __align__(128) float g_YR[NN * NN];
__device__ __align__(128) float g_YI[NN * NN];
__device__ __align__(128) float g_GR[NN * NN];
__device__ __align__(128) float g_GI[NN * NN];
__device__ __align__(128) float g_PR[NN * FOUT];
__device__ __align__(128) float g_PI[NN * FOUT];
__device__ __align__(128) float g_ACC[NN * FOUT];
__device__ __align__(128) float g_OUT0[NN * FOUT];
__device__ __align__(128) float g_dr[NN];
__device__ __align__(128) float g_di[NN];

// ---------------- tf32 helpers ------------------------------------------------
__device__ __forceinline__ uint32_t f2tf(float x) {
    uint32_t u;
    asm("cvt.rna.tf32.f32 %0, %1;" : "=r"(u) : "f"(x));
    return u;
}

__device__ __forceinline__ void mma8(float c[4],
                                     uint32_t a0, uint32_t a1, uint32_t a2, uint32_t a3,
                                     uint32_t b0, uint32_t b1) {
    asm volatile(
        "mma.sync.aligned.m16n8k8.row.col.f32.tf32.tf32.f32 "
        "{%0,%1,%2,%3}, {%4,%5,%6,%7}, {%8,%9}, {%0,%1,%2,%3};"
        : "+f"(c[0]), "+f"(c[1]), "+f"(c[2]), "+f"(c[3])
        : "r"(a0), "r"(a1), "r"(a2), "r"(a3), "r"(b0), "r"(b1));
}

// ---------------- GEMM: C = beta*C + alpha * A(MxK) @ B(KxNC), row-major ------
// SPLIT=true: hi/lo tf32 split (fp32-accurate). SPLIT=false: plain tf32.
// Requires M%128==0, NC%128==0, K%16==0.
template <bool SPLIT>
__global__ void __launch_bounds__(256)
gemm_tf32(const float* __restrict__ A, const float* __restrict__ B,
          float* __restrict__ C, int M, int NC, int K, float alpha, int beta) {
    constexpr int BK = 16, LDA = 136, LDB = 136;
    __shared__ float As[2][BK][LDA];  // transposed: As[k][m]
    __shared__ float Bs[2][BK][LDB];  // Bs[k][n]

    const int tid  = threadIdx.x;
    const int lane = tid & 31;
    const int warp = tid >> 5;
    const int wrow = warp >> 2;   // 0..1
    const int wcol = warp & 3;    // 0..3
    const int g    = lane >> 2;   // 0..7
    const int t    = lane & 3;    // 0..3
    const int bM   = blockIdx.y * 128;
    const int bN   = blockIdx.x * 128;

    const int am  = tid >> 2;          // A tile row (0..63), also +64
    const int ak4 = (tid & 3) * 4;     // A tile k start
    const int bk  = tid >> 5;          // B tile k row (0..7), also +8
    const int bn4 = (tid & 31) * 4;    // B tile n start

    const float* Ag = A + (size_t)(bM + am) * K + ak4;
    const float* Bg = B + (size_t)bk * NC + bN + bn4;
    const size_t Astride = (size_t)64 * K;
    const size_t Bstride = (size_t)8 * NC;

    float acc[4][4][4];
#pragma unroll
    for (int i = 0; i < 4; i++)
#pragma unroll
        for (int j = 0; j < 4; j++)
#pragma unroll
            for (int k = 0; k < 4; k++) acc[i][j][k] = 0.f;

    const int nT = K / BK;
    float4 ra0, ra1, rb0, rb1;

    // prologue: tile 0
    ra0 = *(const float4*)(Ag);
    ra1 = *(const float4*)(Ag + Astride);
    rb0 = *(const float4*)(Bg);
    rb1 = *(const float4*)(Bg + Bstride);
    As[0][ak4 + 0][am] = ra0.x; As[0][ak4 + 1][am] = ra0.y;
    As[0][ak4 + 2][am] = ra0.z; As[0][ak4 + 3][am] = ra0.w;
    As[0][ak4 + 0][am + 64] = ra1.x; As[0][ak4 + 1][am + 64] = ra1.y;
    As[0][ak4 + 2][am + 64] = ra1.z; As[0][ak4 + 3][am + 64] = ra1.w;
    *(float4*)&Bs[0][bk][bn4] = rb0;
    *(float4*)&Bs[0][bk + 8][bn4] = rb1;
    __syncthreads();

    for (int kt = 0; kt < nT; kt++) {
        const int buf = kt & 1;
        if (kt + 1 < nT) {
            const float* Ap = Ag + (size_t)(kt + 1) * BK;
            const float* Bp = Bg + (size_t)(kt + 1) * BK * NC;
            ra0 = *(const float4*)(Ap);
            ra1 = *(const float4*)(Ap + Astride);
            rb0 = *(const float4*)(Bp);
            rb1 = *(const float4*)(Bp + Bstride);
        }
#pragma unroll
        for (int ks = 0; ks < 2; ks++) {
            const int kb = ks * 8;
            float af[4][4], bf[4][2];
#pragma unroll
            for (int mt = 0; mt < 4; mt++) {
                const int m0 = wrow * 64 + mt * 16 + g;
                af[mt][0] = As[buf][kb + t][m0];
                af[mt][1] = As[buf][kb + t][m0 + 8];
                af[mt][2] = As[buf][kb + t + 4][m0];
                af[mt][3] = As[buf][kb + t + 4][m0 + 8];
            }
#pragma unroll
            for (int nt = 0; nt < 4; nt++) {
                const int n0 = wcol * 32 + nt * 8 + g;
                bf[nt][0] = Bs[buf][kb + t][n0];
                bf[nt][1] = Bs[buf][kb + t + 4][n0];
            }
            if (!SPLIT) {
                uint32_t ua[4][4], ub[4][2];
#pragma unroll
                for (int mt = 0; mt < 4; mt++)
#pragma unroll
                    for (int i = 0; i < 4; i++) ua[mt][i] = f2tf(af[mt][i]);
#pragma unroll
                for (int nt = 0; nt < 4; nt++) {
                    ub[nt][0] = f2tf(bf[nt][0]);
                    ub[nt][1] = f2tf(bf[nt][1]);
                }
#pragma unroll
                for (int mt = 0; mt < 4; mt++)
#pragma unroll
                    for (int nt = 0; nt < 4; nt++)
                        mma8(acc[mt][nt], ua[mt][0], ua[mt][1], ua[mt][2], ua[mt][3],
                             ub[nt][0], ub[nt][1]);
            } else {
                uint32_t ah[4][4], al[4][4], bh[4][2], bl[4][2];
#pragma unroll
                for (int mt = 0; mt < 4; mt++)
#pragma unroll
                    for (int i = 0; i < 4; i++) {
                        uint32_t hb = f2tf(af[mt][i]);
                        ah[mt][i] = hb;
                        al[mt][i] = f2tf(af[mt][i] - __uint_as_float(hb));
                    }
#pragma unroll
                for (int nt = 0; nt < 4; nt++)
#pragma unroll
                    for (int i = 0; i < 2; i++) {
                        uint32_t hb = f2tf(bf[nt][i]);
                        bh[nt][i] = hb;
                        bl[nt][i] = f2tf(bf[nt][i] - __uint_as_float(hb));
                    }
#pragma unroll
                for (int mt = 0; mt < 4; mt++)
#pragma unroll
                    for (int nt = 0; nt < 4; nt++) {
                        mma8(acc[mt][nt], al[mt][0], al[mt][1], al[mt][2], al[mt][3],
                             bh[nt][0], bh[nt][1]);
                        mma8(acc[mt][nt], ah[mt][0], ah[mt][1], ah[mt][2], ah[mt][3],
                             bl[nt][0], bl[nt][1]);
                        mma8(acc[mt][nt], ah[mt][0], ah[mt][1], ah[mt][2], ah[mt][3],
                             bh[nt][0], bh[nt][1]);
                    }
            }
        }
        if (kt + 1 < nT) {
            const int nb = buf ^ 1;
            As[nb][ak4 + 0][am] = ra0.x; As[nb][ak4 + 1][am] = ra0.y;
            As[nb][ak4 + 2][am] = ra0.z; As[nb][ak4 + 3][am] = ra0.w;
            As[nb][ak4 + 0][am + 64] = ra1.x; As[nb][ak4 + 1][am + 64] = ra1.y;
            As[nb][ak4 + 2][am + 64] = ra1.z; As[nb][ak4 + 3][am + 64] = ra1.w;
            *(float4*)&Bs[nb][bk][bn4] = rb0;
            *(float4*)&Bs[nb][bk + 8][bn4] = rb1;
        }
        __syncthreads();
    }

    // epilogue
#pragma unroll
    for (int mt = 0; mt < 4; mt++) {
        const int row = bM + wrow * 64 + mt * 16 + g;
#pragma unroll
        for (int nt = 0; nt < 4; nt++) {
            const int col = bN + wcol * 32 + nt * 8 + 2 * t;
            float* p = C + (size_t)row * NC + col;
            if (beta) {
                p[0]                  += alpha * acc[mt][nt][0];
                p[1]                  += alpha * acc[mt][nt][1];
                p[(size_t)8 * NC]     += alpha * acc[mt][nt][2];
                p[(size_t)8 * NC + 1] += alpha * acc[mt][nt][3];
            } else {
                p[0]                  = alpha * acc[mt][nt][0];
                p[1]                  = alpha * acc[mt][nt][1];
                p[(size_t)8 * NC]     = alpha * acc[mt][nt][2];
                p[(size_t)8 * NC + 1] = alpha * acc[mt][nt][3];
            }
        }
    }
}

// ---------------- elementwise kernels -----------------------------------------

// s = h*(1 - rowsum(adj));  d = 1/(s + i) = (s - i)/(s^2+1)
__global__ void rowsum_kernel(const float* __restrict__ adj, const float* __restrict__ hp,
                              float* __restrict__ dr, float* __restrict__ di) {
    __shared__ float sh[256];
    const int row = blockIdx.x;
    const float* a = adj + (size_t)row * NN;
    float s = 0.f;
    for (int c = threadIdx.x; c < NN; c += 256) s += a[c];
    sh[threadIdx.x] = s;
    __syncthreads();
    for (int o = 128; o > 0; o >>= 1) {
        if (threadIdx.x < o) sh[threadIdx.x] += sh[threadIdx.x + o];
        __syncthreads();
    }
    if (threadIdx.x == 0) {
        const float h = *hp;
        const float sv = h * (1.0f - sh[0]);
        const float inv = 1.0f / (sv * sv + 1.0f);
        dr[row] = sv * inv;
        di[row] = -inv;
    }
}

// order 0: xj = hL - i*I ; y = xj
__global__ void init0_kernel(const float* __restrict__ adj, const float* __restrict__ hp) {
    const int col = blockIdx.x * blockDim.x + threadIdx.x;
    const int row = blockIdx.y;
    const size_t idx = (size_t)row * NN + col;
    const float h = *hp;
    const float diag = (row == col) ? 1.f : 0.f;
    const float xr = h * (diag - adj[idx]);
    const float xi = (row == col) ? -1.f : 0.f;
    g_XR[idx] = xr; g_XI[idx] = xi;
    g_YR[idx] = xr; g_YI[idx] = xi;
}

// one Jacobi update; G = adj@y already computed.
// Az = hL@y = h*y - h*G ;  r = xj - (Az + i*y) ;  y += d*r
__global__ void jacobi_kernel(const float* __restrict__ hp,
                              const float* __restrict__ dr, const float* __restrict__ di) {
    const int col = blockIdx.x * blockDim.x + threadIdx.x;
    const int row = blockIdx.y;
    const size_t idx = (size_t)row * NN + col;
    const float h = *hp;
    const float yr = g_YR[idx], yi = g_YI[idx];
    const float azr = h * yr - h * g_GR[idx];
    const float azi = h * yi - h * g_GI[idx];
    const float rr = g_XR[idx] - (azr - yi);
    const float ri = g_XI[idx] - (azi + yr);
    const float d_r = dr[row], d_i = di[row];
    g_YR[idx] = yr + d_r * rr - d_i * ri;
    g_YI[idx] = yi + d_r * ri + d_i * rr;
}

// next-order rhs: xj = hL@prev - i*prev (G = adj@prev); y = xj
__global__ void xj_kernel(const float* __restrict__ hp) {
    const int col = blockIdx.x * blockDim.x + threadIdx.x;
    const int row = blockIdx.y;
    const size_t idx = (size_t)row * NN + col;
    const float h = *hp;
    const float pr = g_YR[idx], pi = g_YI[idx];
    const float azr = h * pr - h * g_GR[idx];
    const float azi = h * pi - h * g_GI[idx];
    const float xr = azr + pi;
    const float xi = azi - pr;
    g_XR[idx] = xr; g_XI[idx] = xi;
    g_YR[idx] = xr; g_YI[idx] = xi;
}

// out = relu(out0 + 2*acc)
__global__ void relu_kernel(float* __restrict__ out) {
    const int i = blockIdx.x * blockDim.x + threadIdx.x;
    const float v = g_OUT0[i] + 2.f * g_ACC[i];
    out[i] = v > 0.f ? v : 0.f;
}

// ---------------- orchestration ------------------------------------------------
extern "C" void kernel_launch(void* const* d_in, const int* in_sizes, int n_in,
                              void* d_out, int out_size) {
    const float* x   = (const float*)d_in[0];
    const float* adj = (const float*)d_in[1];
    const float* hp  = (const float*)d_in[2];
    const float* w0  = (const float*)d_in[3];
    const float* wr  = (const float*)d_in[4];
    const float* wi  = (const float*)d_in[5];
    float* out = (float*)d_out;

    float *XR, *XI, *YR, *YI, *GR, *GI, *PR, *PI, *ACC, *OUT0, *dr, *di;
    cudaGetSymbolAddress((void**)&XR, g_XR);
    cudaGetSymbolAddress((void**)&XI, g_XI);
    cudaGetSymbolAddress((void**)&YR, g_YR);
    cudaGetSymbolAddress((void**)&YI, g_YI);
    cudaGetSymbolAddress((void**)&GR, g_GR);
    cudaGetSymbolAddress((void**)&GI, g_GI);
    cudaGetSymbolAddress((void**)&PR, g_PR);
    cudaGetSymbolAddress((void**)&PI, g_PI);
    cudaGetSymbolAddress((void**)&ACC, g_ACC);
    cudaGetSymbolAddress((void**)&OUT0, g_OUT0);
    cudaGetSymbolAddress((void**)&dr, g_dr);
    cudaGetSymbolAddress((void**)&di, g_di);

    const dim3 blk(256);
    const dim3 gridEW(NN / 256, NN);        // elementwise over N x N
    const dim3 gridBig(NN / 128, NN / 128); // 24 x 24
    const dim3 gridP(FOUT / 128, NN / 128); // 2 x 24

    // diag preconditioner
    rowsum_kernel<<<NN, 256>>>(adj, hp, dr, di);

    // out0 = x @ w0  (fp32-accurate split path)
    gemm_tf32<true><<<gridP, blk>>>(x, w0, OUT0, NN, FOUT, FIN, 1.f, 0);

    // ---- order j = 0 ----
    init0_kernel<<<gridEW, blk>>>(adj, hp);
    for (int it = 0; it < 3; it++) {
        gemm_tf32<false><<<gridBig, blk>>>(adj, YR, GR, NN, NN, NN, 1.f, 0);
        gemm_tf32<false><<<gridBig, blk>>>(adj, YI, GI, NN, NN, NN, 1.f, 0);
        jacobi_kernel<<<gridEW, blk>>>(hp, dr, di);
    }
    gemm_tf32<true><<<gridP, blk>>>(x, wr, PR, NN, FOUT, FIN, 1.f, 0);
    gemm_tf32<true><<<gridP, blk>>>(x, wi, PI, NN, FOUT, FIN, 1.f, 0);
    gemm_tf32<true><<<gridP, blk>>>(YR, PR, ACC, NN, FOUT, NN, 1.f, 0);
    gemm_tf32<true><<<gridP, blk>>>(YI, PI, ACC, NN, FOUT, NN, -1.f, 1);

    // ---- order j = 1 ----
    gemm_tf32<false><<<gridBig, blk>>>(adj, YR, GR, NN, NN, NN, 1.f, 0);
    gemm_tf32<false><<<gridBig, blk>>>(adj, YI, GI, NN, NN, NN, 1.f, 0);
    xj_kernel<<<gridEW, blk>>>(hp);
    for (int it = 0; it < 3; it++) {
        gemm_tf32<false><<<gridBig, blk>>>(adj, YR, GR, NN, NN, NN, 1.f, 0);
        gemm_tf32<false><<<gridBig, blk>>>(adj, YI, GI, NN, NN, NN, 1.f, 0);
        jacobi_kernel<<<gridEW, blk>>>(hp, dr, di);
    }
    gemm_tf32<true><<<gridP, blk>>>(x, wr + FIN * FOUT, PR, NN, FOUT, FIN, 1.f, 0);
    gemm_tf32<true><<<gridP, blk>>>(x, wi + FIN * FOUT, PI, NN, FOUT, FIN, 1.f, 0);
    gemm_tf32<true><<<gridP, blk>>>(YR, PR, ACC, NN, FOUT, NN, 1.f, 1);
    gemm_tf32<true><<<gridP, blk>>>(YI, PI, ACC, NN, FOUT, NN, -1.f, 1);

    // out = relu(out0 + 2*acc)
    relu_kernel<<<(NN * FOUT) / 256, 256>>>(out);
}

// round 2
// speedup vs baseline: 8.7302x; 8.7302x over previous
#include <cuda_runtime.h>
#include <cstdint>
#include <cstddef>

#define NN 3072
#define FB 512     // working block width (256 complex -> 512 real cols)
#define FOUT 256
#define FIN 512

// ---------------- scratch (device globals) -------------------------------------
__device__ __align__(128) float g_Q[NN * FB];
__device__ __align__(128) float g_Y[NN * FB];
__device__ __align__(128) float g_XJ[NN * FB];
__device__ __align__(128) float g_G[3 * NN * FB];   // split-K partials
__device__ __align__(128) float g_OUT0[NN * FOUT];
__device__ __align__(128) float g_dr[NN];
__device__ __align__(128) float g_di[NN];

// ---------------- tf32 helpers ------------------------------------------------
__device__ __forceinline__ uint32_t f2tf(float x) {
    uint32_t u;
    asm("cvt.rna.tf32.f32 %0, %1;" : "=r"(u) : "f"(x));
    return u;
}

__device__ __forceinline__ void mma8(float c[4],
                                     uint32_t a0, uint32_t a1, uint32_t a2, uint32_t a3,
                                     uint32_t b0, uint32_t b1) {
    asm volatile(
        "mma.sync.aligned.m16n8k8.row.col.f32.tf32.tf32.f32 "
        "{%0,%1,%2,%3}, {%4,%5,%6,%7}, {%8,%9}, {%0,%1,%2,%3};"
        : "+f"(c[0]), "+f"(c[1]), "+f"(c[2]), "+f"(c[3])
        : "r"(a0), "r"(a1), "r"(a2), "r"(a3), "r"(b0), "r"(b1));
}

// ---------------- GEMM tile kernel ----------------------------------------------
// C[z] = A(:, z*Kslice : (z+1)*Kslice) @ B(z*Kslice : ..., :)   (row-major)
// Tile: 128x128 per CTA, 256 threads. SPLIT=true -> fp32-accurate 3-mma path.
// !SPLIT stores tf32-pre-rounded values in smem (no cvt in inner loop).
template <bool SPLIT>
__global__ void __launch_bounds__(256)
gemm_tf32(const float* __restrict__ A, int lda,
          const float* __restrict__ B, int ldb,
          float* __restrict__ C, int ldc,
          int Kslice, size_t cPlane) {
    constexpr int BK = 16, LDA = 136, LDB = 136;
    __shared__ float As[2][BK][LDA];  // As[k][m]
    __shared__ float Bs[2][BK][LDB];  // Bs[k][n]

    const int tid  = threadIdx.x;
    const int lane = tid & 31;
    const int warp = tid >> 5;
    const int wrow = warp >> 2;
    const int wcol = warp & 3;
    const int g    = lane >> 2;
    const int t    = lane & 3;
    const int bM   = blockIdx.y * 128;
    const int bN   = blockIdx.x * 128;
    const int kbase = blockIdx.z * Kslice;

    const int am  = tid >> 2;
    const int ak4 = (tid & 3) * 4;
    const int bk  = tid >> 5;
    const int bn4 = (tid & 31) * 4;

    const float* Ag = A + (size_t)(bM + am) * lda + kbase + ak4;
    const float* Bg = B + (size_t)(kbase + bk) * ldb + bN + bn4;
    const size_t Astride = (size_t)64 * lda;
    const size_t Bstride = (size_t)8 * ldb;
    float* Ct = C + blockIdx.z * cPlane;

    float acc[4][4][4];
#pragma unroll
    for (int i = 0; i < 4; i++)
#pragma unroll
        for (int j = 0; j < 4; j++)
#pragma unroll
            for (int k = 0; k < 4; k++) acc[i][j][k] = 0.f;

    const int nT = Kslice / BK;
    float4 ra0, ra1, rb0, rb1;

    auto cvt = [](float v) -> float {
        if (SPLIT) return v;
        uint32_t u;
        asm("cvt.rna.tf32.f32 %0, %1;" : "=r"(u) : "f"(v));
        return __uint_as_float(u);
    };

    // prologue
    ra0 = *(const float4*)(Ag);
    ra1 = *(const float4*)(Ag + Astride);
    rb0 = *(const float4*)(Bg);
    rb1 = *(const float4*)(Bg + Bstride);
    As[0][ak4 + 0][am] = cvt(ra0.x); As[0][ak4 + 1][am] = cvt(ra0.y);
    As[0][ak4 + 2][am] = cvt(ra0.z); As[0][ak4 + 3][am] = cvt(ra0.w);
    As[0][ak4 + 0][am + 64] = cvt(ra1.x); As[0][ak4 + 1][am + 64] = cvt(ra1.y);
    As[0][ak4 + 2][am + 64] = cvt(ra1.z); As[0][ak4 + 3][am + 64] = cvt(ra1.w);
    Bs[0][bk][bn4 + 0] = cvt(rb0.x); Bs[0][bk][bn4 + 1] = cvt(rb0.y);
    Bs[0][bk][bn4 + 2] = cvt(rb0.z); Bs[0][bk][bn4 + 3] = cvt(rb0.w);
    Bs[0][bk + 8][bn4 + 0] = cvt(rb1.x); Bs[0][bk + 8][bn4 + 1] = cvt(rb1.y);
    Bs[0][bk + 8][bn4 + 2] = cvt(rb1.z); Bs[0][bk + 8][bn4 + 3] = cvt(rb1.w);
    __syncthreads();

    for (int kt = 0; kt < nT; kt++) {
        const int buf = kt & 1;
        if (kt + 1 < nT) {
            const float* Ap = Ag + (size_t)(kt + 1) * BK;
            const float* Bp = Bg + (size_t)(kt + 1) * BK * ldb;
            ra0 = *(const float4*)(Ap);
            ra1 = *(const float4*)(Ap + Astride);
            rb0 = *(const float4*)(Bp);
            rb1 = *(const float4*)(Bp + Bstride);
        }
#pragma unroll
        for (int ks = 0; ks < 2; ks++) {
            const int kb = ks * 8;
            float af[4][4], bf[4][2];
#pragma unroll
            for (int mt = 0; mt < 4; mt++) {
                const int m0 = wrow * 64 + mt * 16 + g;
                af[mt][0] = As[buf][kb + t][m0];
                af[mt][1] = As[buf][kb + t][m0 + 8];
                af[mt][2] = As[buf][kb + t + 4][m0];
                af[mt][3] = As[buf][kb + t + 4][m0 + 8];
            }
#pragma unroll
            for (int nt = 0; nt < 4; nt++) {
                const int n0 = wcol * 32 + nt * 8 + g;
                bf[nt][0] = Bs[buf][kb + t][n0];
                bf[nt][1] = Bs[buf][kb + t + 4][n0];
            }
            if (!SPLIT) {
#pragma unroll
                for (int mt = 0; mt < 4; mt++)
#pragma unroll
                    for (int nt = 0; nt < 4; nt++)
                        mma8(acc[mt][nt],
                             __float_as_uint(af[mt][0]), __float_as_uint(af[mt][1]),
                             __float_as_uint(af[mt][2]), __float_as_uint(af[mt][3]),
                             __float_as_uint(bf[nt][0]), __float_as_uint(bf[nt][1]));
            } else {
                uint32_t ah[4][4], al[4][4], bh[4][2], bl[4][2];
#pragma unroll
                for (int mt = 0; mt < 4; mt++)
#pragma unroll
                    for (int i = 0; i < 4; i++) {
                        uint32_t hb = f2tf(af[mt][i]);
                        ah[mt][i] = hb;
                        al[mt][i] = f2tf(af[mt][i] - __uint_as_float(hb));
                    }
#pragma unroll
                for (int nt = 0; nt < 4; nt++)
#pragma unroll
                    for (int i = 0; i < 2; i++) {
                        uint32_t hb = f2tf(bf[nt][i]);
                        bh[nt][i] = hb;
                        bl[nt][i] = f2tf(bf[nt][i] - __uint_as_float(hb));
                    }
#pragma unroll
                for (int mt = 0; mt < 4; mt++)
#pragma unroll
                    for (int nt = 0; nt < 4; nt++) {
                        mma8(acc[mt][nt], al[mt][0], al[mt][1], al[mt][2], al[mt][3],
                             bh[nt][0], bh[nt][1]);
                        mma8(acc[mt][nt], ah[mt][0], ah[mt][1], ah[mt][2], ah[mt][3],
                             bl[nt][0], bl[nt][1]);
                        mma8(acc[mt][nt], ah[mt][0], ah[mt][1], ah[mt][2], ah[mt][3],
                             bh[nt][0], bh[nt][1]);
                    }
            }
        }
        if (kt + 1 < nT) {
            const int nb = buf ^ 1;
            As[nb][ak4 + 0][am] = cvt(ra0.x); As[nb][ak4 + 1][am] = cvt(ra0.y);
            As[nb][ak4 + 2][am] = cvt(ra0.z); As[nb][ak4 + 3][am] = cvt(ra0.w);
            As[nb][ak4 + 0][am + 64] = cvt(ra1.x); As[nb][ak4 + 1][am + 64] = cvt(ra1.y);
            As[nb][ak4 + 2][am + 64] = cvt(ra1.z); As[nb][ak4 + 3][am + 64] = cvt(ra1.w);
            Bs[nb][bk][bn4 + 0] = cvt(rb0.x); Bs[nb][bk][bn4 + 1] = cvt(rb0.y);
            Bs[nb][bk][bn4 + 2] = cvt(rb0.z); Bs[nb][bk][bn4 + 3] = cvt(rb0.w);
            Bs[nb][bk + 8][bn4 + 0] = cvt(rb1.x); Bs[nb][bk + 8][bn4 + 1] = cvt(rb1.y);
            Bs[nb][bk + 8][bn4 + 2] = cvt(rb1.z); Bs[nb][bk + 8][bn4 + 3] = cvt(rb1.w);
        }
        __syncthreads();
    }

#pragma unroll
    for (int mt = 0; mt < 4; mt++) {
        const int row = bM + wrow * 64 + mt * 16 + g;
#pragma unroll
        for (int nt = 0; nt < 4; nt++) {
            const int col = bN + wcol * 32 + nt * 8 + 2 * t;
            float* p = Ct + (size_t)row * ldc + col;
            p[0]                  = acc[mt][nt][0];
            p[1]                  = acc[mt][nt][1];
            p[(size_t)8 * ldc]     = acc[mt][nt][2];
            p[(size_t)8 * ldc + 1] = acc[mt][nt][3];
        }
    }
}

// ---------------- elementwise kernels -------------------------------------------

// s = h*(1 - rowsum(adj)); d = (s - i)/(s^2+1)
__global__ void rowsum_kernel(const float* __restrict__ adj, const float* __restrict__ hp,
                              float* __restrict__ dr, float* __restrict__ di) {
    __shared__ float sh[256];
    const int row = blockIdx.x;
    const float* a = adj + (size_t)row * NN;
    float s = 0.f;
    for (int c = threadIdx.x; c < NN; c += 256) s += a[c];
    sh[threadIdx.x] = s;
    __syncthreads();
    for (int o = 128; o > 0; o >>= 1) {
        if (threadIdx.x < o) sh[threadIdx.x] += sh[threadIdx.x + o];
        __syncthreads();
    }
    if (threadIdx.x == 0) {
        const float h = *hp;
        const float sv = h * (1.0f - sh[0]);
        const float inv = 1.0f / (sv * sv + 1.0f);
        dr[row] = sv * inv;
        di[row] = -inv;
    }
}

// xj = (hL - iI)@Q = h*Q - h*(adj@Q) - i*Q ; Y = XJ = xj.  G = 3 split-K partials of adj@Q.
__global__ void xj_kernel(const float* __restrict__ hp) {
    const int r = blockIdx.x;
    const int c = threadIdx.x;                 // 0..255 (complex pair)
    const size_t idx  = (size_t)r * FB + c;
    const size_t idxI = idx + 256;
    const float h = *hp;
    const size_t P = (size_t)NN * FB;
    const float GR = g_G[idx] + g_G[idx + P] + g_G[idx + 2 * P];
    const float GI = g_G[idxI] + g_G[idxI + P] + g_G[idxI + 2 * P];
    const float qr = g_Q[idx], qi = g_Q[idxI];
    const float xr = h * qr - h * GR + qi;
    const float xi = h * qi - h * GI - qr;
    g_XJ[idx] = xr; g_XJ[idxI] = xi;
    g_Y[idx]  = xr; g_Y[idxI]  = xi;
}

// one Jacobi update: Y += D^{-1}(XJ - (h*Y - h*(adj@Y) + i*Y))
__global__ void jacobi_kernel(const float* __restrict__ hp,
                              const float* __restrict__ dr, const float* __restrict__ di) {
    const int r = blockIdx.x;
    const int c = threadIdx.x;
    const size_t idx  = (size_t)r * FB + c;
    const size_t idxI = idx + 256;
    const float h = *hp;
    const size_t P = (size_t)NN * FB;
    const float GR = g_G[idx] + g_G[idx + P] + g_G[idx + 2 * P];
    const float GI = g_G[idxI] + g_G[idxI + P] + g_G[idxI + 2 * P];
    const float yr = g_Y[idx], yi = g_Y[idxI];
    const float azr = h * yr - h * GR;
    const float azi = h * yi - h * GI;
    const float rr = g_XJ[idx]  - (azr - yi);
    const float ri = g_XJ[idxI] - (azi + yr);
    const float d_r = dr[r], d_i = di[r];
    g_Y[idx]  = yr + d_r * rr - d_i * ri;
    g_Y[idxI] = yi + d_r * ri + d_i * rr;
}

// Q += Y
__global__ void addY_kernel() {
    const size_t i = (size_t)blockIdx.x * blockDim.x + threadIdx.x;
    g_Q[i] += g_Y[i];
}

// out = relu(out0 + 2*Re(Y))
__global__ void relu_kernel(float* __restrict__ out) {
    const int i = blockIdx.x * blockDim.x + threadIdx.x;
    const int r = i >> 8;          // /256
    const int c = i & 255;
    const float v = g_OUT0[i] + 2.f * g_Y[(size_t)r * FB + c];
    out[i] = v > 0.f ? v : 0.f;
}

// ---------------- orchestration --------------------------------------------------
static void applyK(const float* adj, const float* hp, const float* dr, const float* di,
                   float* Q, float* Y, float* G) {
    const dim3 blk(256);
    const dim3 gridBig(4, 24, 3);   // N=512/128, M=3072/128, splitK=3
    // xj = (hL - iI) @ Q
    gemm_tf32<false><<<gridBig, blk>>>(adj, NN, Q, FB, G, FB, 1024, (size_t)NN * FB);
    xj_kernel<<<NN, 256>>>(hp);
    for (int it = 0; it < 3; it++) {
        gemm_tf32<false><<<gridBig, blk>>>(adj, NN, Y, FB, G, FB, 1024, (size_t)NN * FB);
        jacobi_kernel<<<NN, 256>>>(hp, dr, di);
    }
}

extern "C" void kernel_launch(void* const* d_in, const int* in_sizes, int n_in,
                              void* d_out, int out_size) {
    const float* x   = (const float*)d_in[0];
    const float* adj = (const float*)d_in[1];
    const float* hp  = (const float*)d_in[2];
    const float* w0  = (const float*)d_in[3];
    const float* wr  = (const float*)d_in[4];
    const float* wi  = (const float*)d_in[5];
    float* out = (float*)d_out;

    float *Q, *Y, *XJ, *G, *OUT0, *dr, *di;
    cudaGetSymbolAddress((void**)&Q, g_Q);
    cudaGetSymbolAddress((void**)&Y, g_Y);
    cudaGetSymbolAddress((void**)&XJ, g_XJ);
    cudaGetSymbolAddress((void**)&G, g_G);
    cudaGetSymbolAddress((void**)&OUT0, g_OUT0);
    cudaGetSymbolAddress((void**)&dr, g_dr);
    cudaGetSymbolAddress((void**)&di, g_di);

    const dim3 blk(256);
    const dim3 gridSmall(2, 24, 1);  // N=256/128, M=3072/128

    // diag preconditioner
    rowsum_kernel<<<NN, 256>>>(adj, hp, dr, di);

    // P2 = x @ W[1]  -> Q (real plane cols 0:256, imag 256:512)
    gemm_tf32<true><<<gridSmall, blk>>>(x, FIN, wr + FIN * FOUT, FOUT, Q, FB, FIN, 0);
    gemm_tf32<true><<<gridSmall, blk>>>(x, FIN, wi + FIN * FOUT, FOUT, Q + 256, FB, FIN, 0);

    // Z2 = K @ P2
    applyK(adj, hp, dr, di, Q, Y, G);

    // Q = P1 + Z2
    gemm_tf32<true><<<gridSmall, blk>>>(x, FIN, wr, FOUT, Q, FB, FIN, 0);
    gemm_tf32<true><<<gridSmall, blk>>>(x, FIN, wi, FOUT, Q + 256, FB, FIN, 0);
    addY_kernel<<<(NN * FB) / 256, 256>>>();

    // csum = K @ Q
    applyK(adj, hp, dr, di, Q, Y, G);

    // out0 = x @ w0
    gemm_tf32<true><<<gridSmall, blk>>>(x, FIN, w0, FOUT, OUT0, FOUT, FIN, 0);

    // out = relu(out0 + 2*Re(csum))
    relu_kernel<<<(NN * FOUT) / 256, 256>>>(out);
}

// round 3
// speedup vs baseline: 10.6560x; 1.2206x over previous
#include <cuda_runtime.h>
#include <cstdint>
#include <cstddef>

#define NN 3072
#define FB 512     // working block width (256 complex -> 512 real cols)
#define FOUT 256
#define FIN 512

// ---------------- scratch (device globals) -------------------------------------
__device__ __align__(128) float g_Q[NN * FB];
__device__ __align__(128) float g_Y[NN * FB];
__device__ __align__(128) float g_XJ[NN * FB];
__device__ __align__(128) float g_G[3 * NN * FB];   // split-K partials
__device__ __align__(128) float g_OUT0[NN * FOUT];
__device__ __align__(128) float g_W[2 * FIN * FB];  // packed [wr[j] | wi[j]]
__device__ __align__(128) float g_dr[NN];
__device__ __align__(128) float g_di[NN];

// ---------------- tf32 helpers ------------------------------------------------
__device__ __forceinline__ uint32_t f2tf(float x) {
    uint32_t u;
    asm("cvt.rna.tf32.f32 %0, %1;" : "=r"(u) : "f"(x));
    return u;
}

__device__ __forceinline__ void mma8(float c[4],
                                     uint32_t a0, uint32_t a1, uint32_t a2, uint32_t a3,
                                     uint32_t b0, uint32_t b1) {
    asm volatile(
        "mma.sync.aligned.m16n8k8.row.col.f32.tf32.tf32.f32 "
        "{%0,%1,%2,%3}, {%4,%5,%6,%7}, {%8,%9}, {%0,%1,%2,%3};"
        : "+f"(c[0]), "+f"(c[1]), "+f"(c[2]), "+f"(c[3])
        : "r"(a0), "r"(a1), "r"(a2), "r"(a3), "r"(b0), "r"(b1));
}

// ---------------- GEMM tile kernel ----------------------------------------------
// C[z] = A(:, z*Kslice:(z+1)*Kslice) @ B(z*Kslice:..., :)   row-major.
// Tile 128x128, 256 threads. A stored in fragment-ready permuted layout so each
// thread's 4-reg A fragment is one LDS.128.
// A smem layout: Asp[stage][k8][t][mg][4], q = ksel*2 + msel
//   element (m,k): t=k&3, ksel=(k>>2)&1, k8=k>>3, mg=(m&7)|((m>>4)<<3), msel=(m>>3)&1
//   strides (floats): t: 264 (pad 66 float4), k8: 1056, stage: 2112
template <bool SPLIT>
__global__ void __launch_bounds__(256)
gemm_tf32(const float* __restrict__ A, int lda,
          const float* __restrict__ B, int ldb,
          float* __restrict__ C, int ldc,
          int Kslice, size_t cPlane) {
    constexpr int BK = 16, LDB = 136;
    constexpr int AT = 264, AK8 = 1056, AST = 2112;
    __shared__ float Asp[2 * AST];
    __shared__ float Bs[2][BK][LDB];

    const int tid  = threadIdx.x;
    const int lane = tid & 31;
    const int warp = tid >> 5;
    const int wrow = warp >> 2;
    const int wcol = warp & 3;
    const int g    = lane >> 2;
    const int t    = lane & 3;
    const int bM   = blockIdx.y * 128;
    const int bN   = blockIdx.x * 128;
    const int kbase = blockIdx.z * Kslice;

    // A gmem->smem mapping
    const int am   = tid >> 2;           // rows am and am+64
    const int ac   = tid & 3;
    const int ak4  = ac * 4;
    const int k8s  = ac >> 1;
    const int ksel = ac & 1;
    const int mg0  = (am & 7) | ((am >> 4) << 3);
    const int msel = (am >> 3) & 1;
    const int aoff0 = k8s * AK8 + mg0 * 4 + ksel * 2 + msel;        // + j*AT
    const int aoff1 = aoff0 + 32 * 4;                                // row am+64 -> mg+32

    // B gmem->smem mapping
    const int bk  = tid >> 5;
    const int bn4 = (tid & 31) * 4;

    const float* Ag = A + (size_t)(bM + am) * lda + kbase + ak4;
    const float* Bg = B + (size_t)(kbase + bk) * ldb + bN + bn4;
    const size_t Astride = (size_t)64 * lda;
    const size_t Bstride = (size_t)8 * ldb;
    float* Ct = C + blockIdx.z * cPlane;

    float acc[4][4][4];
#pragma unroll
    for (int i = 0; i < 4; i++)
#pragma unroll
        for (int j = 0; j < 4; j++)
#pragma unroll
            for (int k = 0; k < 4; k++) acc[i][j][k] = 0.f;

    const int nT = Kslice / BK;
    float4 ra0, ra1, rb0, rb1;

    auto cvt = [](float v) -> float {
        if (SPLIT) return v;
        uint32_t u;
        asm("cvt.rna.tf32.f32 %0, %1;" : "=r"(u) : "f"(v));
        return __uint_as_float(u);
    };

    auto storeTile = [&](int buf, const float4& a0v, const float4& a1v,
                         const float4& b0v, const float4& b1v) {
        float* Ab = Asp + buf * AST;
        Ab[aoff0 + 0 * AT] = cvt(a0v.x); Ab[aoff0 + 1 * AT] = cvt(a0v.y);
        Ab[aoff0 + 2 * AT] = cvt(a0v.z); Ab[aoff0 + 3 * AT] = cvt(a0v.w);
        Ab[aoff1 + 0 * AT] = cvt(a1v.x); Ab[aoff1 + 1 * AT] = cvt(a1v.y);
        Ab[aoff1 + 2 * AT] = cvt(a1v.z); Ab[aoff1 + 3 * AT] = cvt(a1v.w);
        Bs[buf][bk][bn4 + 0] = cvt(b0v.x); Bs[buf][bk][bn4 + 1] = cvt(b0v.y);
        Bs[buf][bk][bn4 + 2] = cvt(b0v.z); Bs[buf][bk][bn4 + 3] = cvt(b0v.w);
        Bs[buf][bk + 8][bn4 + 0] = cvt(b1v.x); Bs[buf][bk + 8][bn4 + 1] = cvt(b1v.y);
        Bs[buf][bk + 8][bn4 + 2] = cvt(b1v.z); Bs[buf][bk + 8][bn4 + 3] = cvt(b1v.w);
    };

    // prologue
    ra0 = *(const float4*)(Ag);
    ra1 = *(const float4*)(Ag + Astride);
    rb0 = *(const float4*)(Bg);
    rb1 = *(const float4*)(Bg + Bstride);
    storeTile(0, ra0, ra1, rb0, rb1);
    __syncthreads();

    for (int kt = 0; kt < nT; kt++) {
        const int buf = kt & 1;
        if (kt + 1 < nT) {
            const float* Ap = Ag + (size_t)(kt + 1) * BK;
            const float* Bp = Bg + (size_t)(kt + 1) * BK * ldb;
            ra0 = *(const float4*)(Ap);
            ra1 = *(const float4*)(Ap + Astride);
            rb0 = *(const float4*)(Bp);
            rb1 = *(const float4*)(Bp + Bstride);
        }
        const float* Ab = Asp + buf * AST + t * AT;
#pragma unroll
        for (int ks = 0; ks < 2; ks++) {
            const int kb = ks * 8;
            float4 afv[4];
            float bf[4][2];
#pragma unroll
            for (int mt = 0; mt < 4; mt++)
                afv[mt] = *(const float4*)(Ab + ks * AK8 + ((wrow * 4 + mt) * 8 + g) * 4);
#pragma unroll
            for (int nt = 0; nt < 4; nt++) {
                const int n0 = wcol * 32 + nt * 8 + g;
                bf[nt][0] = Bs[buf][kb + t][n0];
                bf[nt][1] = Bs[buf][kb + t + 4][n0];
            }
            if (!SPLIT) {
#pragma unroll
                for (int mt = 0; mt < 4; mt++)
#pragma unroll
                    for (int nt = 0; nt < 4; nt++)
                        mma8(acc[mt][nt],
                             __float_as_uint(afv[mt].x), __float_as_uint(afv[mt].y),
                             __float_as_uint(afv[mt].z), __float_as_uint(afv[mt].w),
                             __float_as_uint(bf[nt][0]), __float_as_uint(bf[nt][1]));
            } else {
                uint32_t ah[4][4], al[4][4], bh[4][2], bl[4][2];
#pragma unroll
                for (int mt = 0; mt < 4; mt++) {
                    const float a4[4] = {afv[mt].x, afv[mt].y, afv[mt].z, afv[mt].w};
#pragma unroll
                    for (int i = 0; i < 4; i++) {
                        uint32_t hb = f2tf(a4[i]);
                        ah[mt][i] = hb;
                        al[mt][i] = f2tf(a4[i] - __uint_as_float(hb));
                    }
                }
#pragma unroll
                for (int nt = 0; nt < 4; nt++)
#pragma unroll
                    for (int i = 0; i < 2; i++) {
                        uint32_t hb = f2tf(bf[nt][i]);
                        bh[nt][i] = hb;
                        bl[nt][i] = f2tf(bf[nt][i] - __uint_as_float(hb));
                    }
#pragma unroll
                for (int mt = 0; mt < 4; mt++)
#pragma unroll
                    for (int nt = 0; nt < 4; nt++) {
                        mma8(acc[mt][nt], al[mt][0], al[mt][1], al[mt][2], al[mt][3],
                             bh[nt][0], bh[nt][1]);
                        mma8(acc[mt][nt], ah[mt][0], ah[mt][1], ah[mt][2], ah[mt][3],
                             bl[nt][0], bl[nt][1]);
                        mma8(acc[mt][nt], ah[mt][0], ah[mt][1], ah[mt][2], ah[mt][3],
                             bh[nt][0], bh[nt][1]);
                    }
            }
        }
        if (kt + 1 < nT) storeTile(buf ^ 1, ra0, ra1, rb0, rb1);
        __syncthreads();
    }

#pragma unroll
    for (int mt = 0; mt < 4; mt++) {
        const int row = bM + wrow * 64 + mt * 16 + g;
#pragma unroll
        for (int nt = 0; nt < 4; nt++) {
            const int col = bN + wcol * 32 + nt * 8 + 2 * t;
            float* p = Ct + (size_t)row * ldc + col;
            p[0]                   = acc[mt][nt][0];
            p[1]                   = acc[mt][nt][1];
            p[(size_t)8 * ldc]     = acc[mt][nt][2];
            p[(size_t)8 * ldc + 1] = acc[mt][nt][3];
        }
    }
}

// ---------------- elementwise kernels -------------------------------------------

__global__ void rowsum_kernel(const float* __restrict__ adj, const float* __restrict__ hp,
                              float* __restrict__ dr, float* __restrict__ di) {
    __shared__ float sh[256];
    const int row = blockIdx.x;
    const float* a = adj + (size_t)row * NN;
    float s = 0.f;
    for (int c = threadIdx.x; c < NN; c += 256) s += a[c];
    sh[threadIdx.x] = s;
    __syncthreads();
    for (int o = 128; o > 0; o >>= 1) {
        if (threadIdx.x < o) sh[threadIdx.x] += sh[threadIdx.x + o];
        __syncthreads();
    }
    if (threadIdx.x == 0) {
        const float h = *hp;
        const float sv = h * (1.0f - sh[0]);
        const float inv = 1.0f / (sv * sv + 1.0f);
        dr[row] = sv * inv;
        di[row] = -inv;
    }
}

// pack g_W[j] = [ wr[j] | wi[j] ]  ([FIN, 512])
__global__ void packW_kernel(const float* __restrict__ wr, const float* __restrict__ wi) {
    const int i = blockIdx.x * blockDim.x + threadIdx.x;   // over 2*FIN*FB
    const int j = i / (FIN * FB);
    const int r = (i / FB) % FIN;
    const int c = i % FB;
    const float v = (c < FOUT) ? wr[(size_t)j * FIN * FOUT + r * FOUT + c]
                               : wi[(size_t)j * FIN * FOUT + r * FOUT + (c - FOUT)];
    g_W[i] = v;
}

// xj = (hL - iI)@Q ; Y = XJ = xj.  G holds 3 split-K partials of adj@Q.
__global__ void xj_kernel(const float* __restrict__ hp) {
    const int r = blockIdx.x;
    const int c = threadIdx.x;
    const size_t idx  = (size_t)r * FB + c;
    const size_t idxI = idx + 256;
    const float h = *hp;
    const size_t P = (size_t)NN * FB;
    const float GR = g_G[idx] + g_G[idx + P] + g_G[idx + 2 * P];
    const float GI = g_G[idxI] + g_G[idxI + P] + g_G[idxI + 2 * P];
    const float qr = g_Q[idx], qi = g_Q[idxI];
    const float xr = h * qr - h * GR + qi;
    const float xi = h * qi - h * GI - qr;
    g_XJ[idx] = xr; g_XJ[idxI] = xi;
    g_Y[idx]  = xr; g_Y[idxI]  = xi;
}

__global__ void jacobi_kernel(const float* __restrict__ hp,
                              const float* __restrict__ dr, const float* __restrict__ di) {
    const int r = blockIdx.x;
    const int c = threadIdx.x;
    const size_t idx  = (size_t)r * FB + c;
    const size_t idxI = idx + 256;
    const float h = *hp;
    const size_t P = (size_t)NN * FB;
    const float GR = g_G[idx] + g_G[idx + P] + g_G[idx + 2 * P];
    const float GI = g_G[idxI] + g_G[idxI + P] + g_G[idxI + 2 * P];
    const float yr = g_Y[idx], yi = g_Y[idxI];
    const float azr = h * yr - h * GR;
    const float azi = h * yi - h * GI;
    const float rr = g_XJ[idx]  - (azr - yi);
    const float ri = g_XJ[idxI] - (azi + yr);
    const float d_r = dr[r], d_i = di[r];
    g_Y[idx]  = yr + d_r * rr - d_i * ri;
    g_Y[idxI] = yi + d_r * ri + d_i * rr;
}

__global__ void addY_kernel() {
    const size_t i = (size_t)blockIdx.x * blockDim.x + threadIdx.x;
    g_Q[i] += g_Y[i];
}

__global__ void relu_kernel(float* __restrict__ out) {
    const int i = blockIdx.x * blockDim.x + threadIdx.x;
    const int r = i >> 8;
    const int c = i & 255;
    const float v = g_OUT0[i] + 2.f * g_Y[(size_t)r * FB + c];
    out[i] = v > 0.f ? v : 0.f;
}

// ---------------- orchestration --------------------------------------------------
static void applyK(const float* adj, const float* hp, const float* dr, const float* di,
                   float* Q, float* Y, float* G) {
    const dim3 blk(256);
    const dim3 gridBig(4, 24, 3);   // N=512/128, M=3072/128, splitK=3
    gemm_tf32<false><<<gridBig, blk>>>(adj, NN, Q, FB, G, FB, 1024, (size_t)NN * FB);
    xj_kernel<<<NN, 256>>>(hp);
    for (int it = 0; it < 3; it++) {
        gemm_tf32<false><<<gridBig, blk>>>(adj, NN, Y, FB, G, FB, 1024, (size_t)NN * FB);
        jacobi_kernel<<<NN, 256>>>(hp, dr, di);
    }
}

extern "C" void kernel_launch(void* const* d_in, const int* in_sizes, int n_in,
                              void* d_out, int out_size) {
    const float* x   = (const float*)d_in[0];
    const float* adj = (const float*)d_in[1];
    const float* hp  = (const float*)d_in[2];
    const float* w0  = (const float*)d_in[3];
    const float* wr  = (const float*)d_in[4];
    const float* wi  = (const float*)d_in[5];
    float* out = (float*)d_out;

    float *Q, *Y, *G, *OUT0, *W, *dr, *di;
    cudaGetSymbolAddress((void**)&Q, g_Q);
    cudaGetSymbolAddress((void**)&Y, g_Y);
    cudaGetSymbolAddress((void**)&G, g_G);
    cudaGetSymbolAddress((void**)&OUT0, g_OUT0);
    cudaGetSymbolAddress((void**)&W, g_W);
    cudaGetSymbolAddress((void**)&dr, g_dr);
    cudaGetSymbolAddress((void**)&di, g_di);

    const dim3 blk(256);
    const dim3 gridP(4, 24, 1);      // N=512/128
    const dim3 gridO(2, 24, 1);      // N=256/128

    rowsum_kernel<<<NN, 256>>>(adj, hp, dr, di);
    packW_kernel<<<(2 * FIN * FB) / 256, 256>>>(wr, wi);

    // Q = P2 = x @ [wr[1]|wi[1]]
    gemm_tf32<true><<<gridP, blk>>>(x, FIN, W + FIN * FB, FB, Q, FB, FIN, 0);

    // Y = K @ P2
    applyK(adj, hp, dr, di, Q, Y, G);

    // Q = P1 + Y
    gemm_tf32<true><<<gridP, blk>>>(x, FIN, W, FB, Q, FB, FIN, 0);
    addY_kernel<<<(NN * FB) / 256, 256>>>();

    // Y = K @ Q  (= csum)
    applyK(adj, hp, dr, di, Q, Y, G);

    // out0 = x @ w0
    gemm_tf32<true><<<gridO, blk>>>(x, FIN, w0, FOUT, OUT0, FOUT, FIN, 0);

    // out = relu(out0 + 2*Re(csum))
    relu_kernel<<<(NN * FOUT) / 256, 256>>>(out);
}